// round 1
// baseline (speedup 1.0000x reference)
#include <cuda_runtime.h>
#include <cstdint>

// YoloLayer: x (64, 30, 152, 152) f32 -> out (64, 3*152*152, 10) f32
// Per (b, a, y, x):
//   out0 = (sigmoid(p0)*1.05 - 0.025 + x) * stride
//   out1 = (sigmoid(p1)*1.05 - 0.025 + y) * stride
//   out2 = exp(p2) * ANCHOR_W[a]      (stride cancels: (aw/stride)*stride)
//   out3 = exp(p3) * ANCHOR_H[a]
//   out4 = p4, out5 = p5
//   out6 = sigmoid(p6)
//   out7..9 = sigmoid(p7..9)
// stride = img_size / g = 1216/152 = 8

#define G    152
#define GG   (G * G)          // 23104 (divisible by 32 -> warps never straddle planes)
#define A    3
#define F    10
#define B    64
#define BLK  256

__constant__ float c_anchor_w[A] = {12.0f, 19.0f, 40.0f};
__constant__ float c_anchor_h[A] = {16.0f, 36.0f, 28.0f};

__device__ __forceinline__ float fsigmoid(float v) {
    return 1.0f / (1.0f + __expf(-v));
}

__global__ __launch_bounds__(BLK) void yolo_kernel(
    const float* __restrict__ x,
    const int*   __restrict__ img,   // scalar, dtype-ambiguous (int32 or f32 bits)
    float*       __restrict__ out)
{
    __shared__ float s[BLK * F];     // 10 KB

    const int tid = threadIdx.x;
    const int p   = blockIdx.x * BLK + tid;   // global position index, exact grid

    // Decode img_size robustly regardless of int32 vs float32 storage.
    int iv = img[0];
    float img_f = (iv > 0 && iv < 1000000) ? (float)iv : __int_as_float(iv);
    const float stride = img_f / (float)G;    // 8.0

    // p -> (b, a, s)
    const int b    = p / (A * GG);
    int rem        = p - b * (A * GG);
    const int a    = rem / GG;
    const int sidx = rem - a * GG;
    const int yy   = sidx / G;
    const int xx   = sidx - yy * G;

    // Input base: ((b*30 + a*10 + f) * GG + sidx)
    const float* base = x + ((size_t)(b * (A * F) + a * F)) * GG + sidx;

    float v[F];
#pragma unroll
    for (int f = 0; f < F; f++)
        v[f] = base[(size_t)f * GG];          // 10 coalesced, independent LDGs

    const float SXY = 1.05f;
    const float OFF = 0.025f;                 // 0.5*(SCALE_XY-1)

    const float aw = c_anchor_w[a];
    const float ah = c_anchor_h[a];

    float r[F];
    r[0] = (fsigmoid(v[0]) * SXY - OFF + (float)xx) * stride;
    r[1] = (fsigmoid(v[1]) * SXY - OFF + (float)yy) * stride;
    r[2] = __expf(v[2]) * aw;
    r[3] = __expf(v[3]) * ah;
    r[4] = v[4];
    r[5] = v[5];
    r[6] = fsigmoid(v[6]);
    r[7] = fsigmoid(v[7]);
    r[8] = fsigmoid(v[8]);
    r[9] = fsigmoid(v[9]);

#pragma unroll
    for (int f = 0; f < F; f++)
        s[tid * F + f] = r[f];                // minor 2-way bank conflict, cheap

    __syncthreads();

    // Block's output slice is exactly BLK*F contiguous floats -> coalesced stores.
    float* ob = out + (size_t)blockIdx.x * (BLK * F);
#pragma unroll
    for (int i = 0; i < F; i++)
        ob[tid + i * BLK] = s[tid + i * BLK];
}

extern "C" void kernel_launch(void* const* d_in, const int* in_sizes, int n_in,
                              void* d_out, int out_size)
{
    const float* x   = (const float*)d_in[0];
    const int*   img = (n_in >= 2) ? (const int*)d_in[1] : nullptr;
    float*       out = (float*)d_out;

    // Total positions = 64*3*152*152 = 4,435,968 = 17328 * 256 exactly.
    const int total = B * A * GG;
    const int grid  = total / BLK;

    yolo_kernel<<<grid, BLK>>>(x, img, out);
}